// round 15
// baseline (speedup 1.0000x reference)
#include <cuda_runtime.h>
#include <cuda_bf16.h>
#include <cuda_fp16.h>
#include <cstdint>
#include <math.h>

// ---------------------------------------------------------------------------
// Problem constants
// ---------------------------------------------------------------------------
#define BATCH   2
#define SEQ     2048
#define HID     2048
#define NH      16
#define NKV     4
#define DH      128
#define KVW     (NKV * DH)          // 512
#define MTOT    (BATCH * SEQ)       // 4096
#define GROUPS  (NH / NKV)          // 4
#define GEMM_K  2048
#define NQKV    (HID + 2 * KVW)     // 3072

// ---------------------------------------------------------------------------
// PTX helpers — ONLY non-'a' features (mma.sync / ldmatrix / cp.async).
// ---------------------------------------------------------------------------
__device__ __forceinline__ uint32_t smem_to_u32(const void* p) {
    uint32_t a;
    asm("{ .reg .u64 t; cvta.to.shared.u64 t, %1; cvt.u32.u64 %0, t; }"
        : "=r"(a) : "l"(p));
    return a;
}
#define CP_ASYNC16(dst, src) \
    asm volatile("cp.async.cg.shared.global [%0], [%1], 16;" \
                 :: "r"(dst), "l"(src))
#define CP_ASYNC4(dst, src) \
    asm volatile("cp.async.ca.shared.global [%0], [%1], 4;" \
                 :: "r"(dst), "l"(src))
#define CP_COMMIT() asm volatile("cp.async.commit_group;")
#define CP_WAIT(n)  asm volatile("cp.async.wait_group %0;" :: "n"(n))

__device__ __forceinline__ void ldsm_x4(uint32_t* r, uint32_t addr) {
    asm volatile("ldmatrix.sync.aligned.m8n8.x4.shared.b16 {%0,%1,%2,%3}, [%4];"
                 : "=r"(r[0]), "=r"(r[1]), "=r"(r[2]), "=r"(r[3]) : "r"(addr));
}
__device__ __forceinline__ void mma_f16(float* d, const uint32_t* a,
                                        const uint32_t* b) {
    asm volatile(
        "mma.sync.aligned.m16n8k16.row.col.f32.f16.f16.f32 "
        "{%0,%1,%2,%3}, {%4,%5,%6,%7}, {%8,%9}, {%0,%1,%2,%3};"
        : "+f"(d[0]), "+f"(d[1]), "+f"(d[2]), "+f"(d[3])
        : "r"(a[0]), "r"(a[1]), "r"(a[2]), "r"(a[3]), "r"(b[0]), "r"(b[1]));
}
__device__ __forceinline__ uint32_t packh2(float x, float y) {
    __half2 h(__float2half(x), __float2half(y));
    return *reinterpret_cast<uint32_t*>(&h);
}
__device__ __forceinline__ float ex2(float x) {
    float r;
    asm("ex2.approx.f32 %0, %1;" : "=f"(r) : "f"(x));
    return r;
}

// ---------------------------------------------------------------------------
// Scratch buffers
// ---------------------------------------------------------------------------
__device__ __half g_xh[(size_t)MTOT * HID];           // x single fp16
__device__ __half g_qs[(size_t)MTOT * HID];           // q single fp16 (pre-scaled)
__device__ __half g_kh[(size_t)MTOT * KVW];           // k single fp16
__device__ __half g_vth[(size_t)MTOT * KVW];          // VT single fp16 [B*KVW, SEQ]
__device__ __half g_ah[(size_t)MTOT * HID];           // attn out fp16
__device__ __half g_wh[(size_t)NQKV * HID];           // [Wq;Wk;Wv] T, single fp16
__device__ __half g_woh[(size_t)HID * HID];           // Wo T, single fp16

// ---------------------------------------------------------------------------
// Single merged converter: x -> fp16 AND all 4 weights transposed -> fp16.
// ---------------------------------------------------------------------------
#define WCONV_BLOCKS (160 * 64)
#define XCONV_BLOCKS (MTOT * HID / 4 / 256)   // 8192

__global__ void conv_kernel(const float* __restrict__ x,
                            const float* __restrict__ Wq,
                            const float* __restrict__ Wk,
                            const float* __restrict__ Wv,
                            const float* __restrict__ Wo,
                            __half* __restrict__ xh,
                            __half* __restrict__ wh,
                            __half* __restrict__ woh)
{
    const int bx  = blockIdx.x;
    const int tid = threadIdx.x;

    if (bx >= WCONV_BLOCKS) {
        const int i = (bx - WCONV_BLOCKS) * 256 + tid;
        float4 v = ((const float4*)x)[i];
        ((uint32_t*)xh)[2*i]   = packh2(v.x, v.y);
        ((uint32_t*)xh)[2*i+1] = packh2(v.z, v.w);
        return;
    }

    const int wmat = bx >> 6;
    const int by   = bx & 63;
    const float* W;
    __half* Th;
    int N, nblk;
    if (wmat < 64)      { W = Wq; Th = wh;  N = HID; nblk = wmat; }
    else if (wmat < 80) { W = Wk; Th = wh + (size_t)HID * GEMM_K;  N = KVW; nblk = wmat - 64; }
    else if (wmat < 96) { W = Wv; Th = wh + (size_t)(HID + KVW) * GEMM_K; N = KVW; nblk = wmat - 80; }
    else                { W = Wo; Th = woh; N = HID; nblk = wmat - 96; }

    __shared__ float t[32][33];
    const int tx = tid & 31, ty = tid >> 5;
    const int n  = nblk * 32 + tx;
    const int kb = by * 32;
    #pragma unroll
    for (int j = 0; j < 32; j += 8)
        t[ty + j][tx] = W[(size_t)(kb + ty + j) * N + n];
    __syncthreads();
    const int k  = kb + tx;
    const int nb = nblk * 32;
    #pragma unroll
    for (int j = 0; j < 32; j += 8) {
        float v = t[tx][ty + j];
        Th[(size_t)(nb + ty + j) * GEMM_K + k] = __float2half(v);
    }
}

// ---------------------------------------------------------------------------
// fp16 HMMA GEMM mainloop: C = A[M,K] @ B^T[N,K]
// 128 threads / 4 warps, warp tile 64x64 (square -> A redundancy 4x->2x,
// smem read traffic per chunk 96KB->64KB: near tensor/smem parity).
// KC=64 chunks, 3-stage pipeline, ONE sync per chunk, bias in smem.
// ---------------------------------------------------------------------------
#define KC        64
#define AS_STRIDE 72
#define MAT_B     (128 * AS_STRIDE * 2)   // 18432 bytes
#define STAGE_B   (2 * MAT_B)             // 36864 bytes
#define NCHUNK    (GEMM_K / KC)           // 32
#define SM_BIAS   (3 * STAGE_B)           // 110592
#define GEMM_SMEM (SM_BIAS + 512)         // 111104

#define GEMM_MAINLOOP_F16(AhP, BhP, BIAS_SRC)                                   \
    float acc[4][8][4];                                                         \
    _Pragma("unroll")                                                           \
    for (int a = 0; a < 4; ++a)                                                 \
        _Pragma("unroll")                                                       \
        for (int b2 = 0; b2 < 8; ++b2)                                          \
            _Pragma("unroll")                                                   \
            for (int c = 0; c < 4; ++c) acc[a][b2][c] = 0.f;                    \
    const __half* mats[2] = {AhP, BhP};                                         \
    auto load_stage = [&](int s, int k0) {                                      \
        const uint32_t st = smem_base + s * STAGE_B;                            \
        _Pragma("unroll")                                                       \
        for (int mat = 0; mat < 2; ++mat) {                                     \
            const __half* src = mats[mat];                                      \
            const int r0 = (mat < 1) ? m0 : n0;                                 \
            const uint32_t dstb = st + mat * MAT_B;                             \
            _Pragma("unroll")                                                   \
            for (int it = 0; it < 8; ++it) {                                    \
                const int idx = it * 128 + tid;                                 \
                const int row = idx >> 3;                                       \
                const int k8  = idx & 7;                                        \
                const void* sp = src + (size_t)(r0 + row) * GEMM_K + k0 + k8*8; \
                const uint32_t dp = dstb + row * (AS_STRIDE * 2) + k8 * 16;     \
                CP_ASYNC16(dp, sp);                                             \
            }                                                                   \
        }                                                                       \
    };                                                                          \
    if (tid < 32) CP_ASYNC16(smem_base + SM_BIAS + tid * 16, (BIAS_SRC) + tid * 4); \
    load_stage(0, 0);                                                           \
    CP_COMMIT();                                                                \
    load_stage(1, KC);                                                          \
    CP_COMMIT();                                                                \
    for (int c = 0; c < NCHUNK; ++c) {                                          \
        if (c + 1 < NCHUNK) { CP_WAIT(1); } else { CP_WAIT(0); }                \
        __syncthreads();                                                        \
        if (c + 2 < NCHUNK) {                                                   \
            load_stage((c + 2) % 3, (c + 2) * KC);                              \
            CP_COMMIT();                                                        \
        }                                                                       \
        const uint32_t stg = smem_base + (c % 3) * STAGE_B;                     \
        const uint32_t pA  = stg;                                               \
        const uint32_t pB  = stg + MAT_B;                                       \
        _Pragma("unroll")                                                       \
        for (int ks = 0; ks < 4; ++ks) {                                        \
            const int kcol = ks * 16;                                           \
            uint32_t bh[16];                                                    \
            _Pragma("unroll")                                                   \
            for (int p = 0; p < 4; ++p) {                                       \
                const int nrow = wn * 64 + p * 16 + (lane & 7) + ((lane>>4)<<3);\
                const int kk   = kcol + (((lane >> 3) & 1) << 3);               \
                const uint32_t off = (nrow * AS_STRIDE + kk) * 2;               \
                ldsm_x4(&bh[p * 4], pB + off);                                  \
            }                                                                   \
            _Pragma("unroll")                                                   \
            for (int mt = 0; mt < 4; ++mt) {                                    \
                const int mrow = wm * 64 + mt * 16 + (lane & 15);               \
                const int kk2  = kcol + ((lane >> 4) << 3);                     \
                const uint32_t offa = (mrow * AS_STRIDE + kk2) * 2;             \
                uint32_t afr[4];                                                \
                ldsm_x4(afr, pA + offa);                                        \
                _Pragma("unroll")                                               \
                for (int nt = 0; nt < 8; ++nt) mma_f16(acc[mt][nt], afr, &bh[nt*2]); \
            }                                                                   \
        }                                                                       \
    }

// ---------------------------------------------------------------------------
// Fused QKV projection: q -> single fp16 (pre-scaled by scl*log2e),
// k -> single fp16, v -> fp16 stored DIRECTLY TRANSPOSED into VT[B*KVW, SEQ].
// ---------------------------------------------------------------------------
#define ATT_SCL (0.08838834764831845f * 1.4426950408889634f)

__global__ void __launch_bounds__(128, 2)
gemm_qkv(const __half* __restrict__ Ah, const __half* __restrict__ Bh,
         const float* __restrict__ bq, const float* __restrict__ bk,
         const float* __restrict__ bv,
         __half* __restrict__ Qs, __half* __restrict__ Kh,
         __half* __restrict__ VT)
{
    extern __shared__ __align__(128) char smem[];
    const uint32_t smem_base = smem_to_u32(smem);
    const int tid  = threadIdx.x;
    const int warp = tid >> 5;
    const int lane = tid & 31;
    const int wm   = warp >> 1;        // 0..1 -> 64 rows
    const int wn   = warp & 1;         // 0..1 -> 64 cols
    const int m0   = blockIdx.y * 128;
    const int n0   = blockIdx.x * 128;

    const float* bsrc = (n0 < HID) ? (bq + n0)
                       : (n0 < HID + KVW) ? (bk + n0 - HID)
                       : (bv + n0 - HID - KVW);

    GEMM_MAINLOOP_F16(Ah, Bh, bsrc)

    const float* bias_s = (const float*)(smem + SM_BIAS);

    #pragma unroll
    for (int mt = 0; mt < 4; ++mt)
        #pragma unroll
        for (int rh = 0; rh < 2; ++rh) {
            const int row = m0 + wm * 64 + mt * 16 + (lane >> 2) + rh * 8;
            #pragma unroll
            for (int nt = 0; nt < 8; ++nt) {
                const int cl  = wn * 64 + nt * 8 + (lane & 3) * 2;  // 0..127
                const int col = n0 + cl;
                const float b0 = bias_s[cl], b1 = bias_s[cl + 1];
                if (n0 < HID) {
                    const float v0 = (acc[mt][nt][rh*2+0] + b0) * ATT_SCL;
                    const float v1 = (acc[mt][nt][rh*2+1] + b1) * ATT_SCL;
                    *(uint32_t*)&Qs[(size_t)row * HID + col] = packh2(v0, v1);
                } else if (n0 < HID + KVW) {
                    const int c2 = col - HID;
                    const float v0 = acc[mt][nt][rh*2+0] + b0;
                    const float v1 = acc[mt][nt][rh*2+1] + b1;
                    *(uint32_t*)&Kh[(size_t)row * KVW + c2] = packh2(v0, v1);
                } else {
                    const int c2 = col - HID - KVW;
                    const int bb = row >> 11;          // / SEQ
                    const int ss = row & (SEQ - 1);
                    const float v0 = acc[mt][nt][rh*2+0] + b0;
                    const float v1 = acc[mt][nt][rh*2+1] + b1;
                    VT[((size_t)bb * KVW + c2)     * SEQ + ss] = __float2half(v0);
                    VT[((size_t)bb * KVW + c2 + 1) * SEQ + ss] = __float2half(v1);
                }
            }
        }
}

// ---------------------------------------------------------------------------
// O-projection GEMM (fp16 single-pass, fp32 out)
// ---------------------------------------------------------------------------
__global__ void __launch_bounds__(128, 2)
gemm_o(const __half* __restrict__ Ah, const __half* __restrict__ Bh,
       const float* __restrict__ bias, float* __restrict__ C)
{
    extern __shared__ __align__(128) char smem[];
    const uint32_t smem_base = smem_to_u32(smem);
    const int tid  = threadIdx.x;
    const int warp = tid >> 5;
    const int lane = tid & 31;
    const int wm   = warp >> 1;
    const int wn   = warp & 1;
    const int m0   = blockIdx.y * 128;
    const int n0   = blockIdx.x * 128;

    GEMM_MAINLOOP_F16(Ah, Bh, bias + n0)

    const float* bias_s = (const float*)(smem + SM_BIAS);

    #pragma unroll
    for (int mt = 0; mt < 4; ++mt)
        #pragma unroll
        for (int rh = 0; rh < 2; ++rh) {
            const int row = m0 + wm * 64 + mt * 16 + (lane >> 2) + rh * 8;
            #pragma unroll
            for (int nt = 0; nt < 8; ++nt) {
                const int cl  = wn * 64 + nt * 8 + (lane & 3) * 2;
                const int col = n0 + cl;
                float2 v;
                v.x = acc[mt][nt][rh*2+0] + bias_s[cl];
                v.y = acc[mt][nt][rh*2+1] + bias_s[cl + 1];
                *(float2*)&C[(size_t)row * HID + col] = v;
            }
        }
}

// ---------------------------------------------------------------------------
// fp16 FlashAttention: 128 q-rows x 64 kv tiles, 8 warps (UNCHANGED from R13).
// ---------------------------------------------------------------------------
#define QSTR 136
#define VSTR 72
#define SM_Q   0
#define SM_ST  34816
#define STG_B  35840
#define SM_MK  (SM_ST + 2 * STG_B)
#define ATTN_SMEM (SM_MK + 512)

__global__ void __launch_bounds__(256, 2)
attn_hmma(const __half* __restrict__ Qs, const __half* __restrict__ Kh,
          const __half* __restrict__ VTh, const int* __restrict__ mask,
          __half* __restrict__ OH)
{
    extern __shared__ __align__(128) char sm[];
    const uint32_t base = smem_to_u32(sm);
    const int tid = threadIdx.x;
    const int w    = tid >> 5;
    const int lane = tid & 31;
    const int h  = blockIdx.x;
    const int qb = (int)gridDim.y - 1 - (int)blockIdx.y;   // heavy-first (LPT)
    const int b  = blockIdx.z;
    const int q0 = qb * 128;
    const int kvh = h >> 2;
    const int T = 2 * qb + 2;

    auto load_kv = [&](int t) {
        const int k0 = t * 64;
        const int s  = t & 1;
        const uint32_t kdst = base + SM_ST + s * STG_B;
        #pragma unroll
        for (int i = 0; i < 4; ++i) {
            const int idx = i * 256 + tid;
            const int row = idx >> 4, c = idx & 15;
            CP_ASYNC16(kdst + row * 272 + c * 16,
                       Kh + (size_t)(b * SEQ + k0 + row) * KVW + kvh * DH + c * 8);
        }
        const uint32_t vdst = kdst + 17408;
        #pragma unroll
        for (int i = 0; i < 4; ++i) {
            const int idx = i * 256 + tid;
            const int row = idx >> 3, c = idx & 7;
            CP_ASYNC16(vdst + row * 144 + c * 16,
                       VTh + (size_t)(b * KVW + kvh * DH + row) * SEQ + k0 + c * 8);
        }
        if (tid < 64)
            CP_ASYNC4(base + SM_MK + s * 256 + tid * 4, mask + b * SEQ + k0 + tid);
    };

    #pragma unroll
    for (int i = 0; i < 8; ++i) {
        const int idx = i * 256 + tid;
        const int row = idx >> 4, c = idx & 15;
        CP_ASYNC16(base + SM_Q + row * 272 + c * 16,
                   Qs + (size_t)(b * SEQ + q0 + row) * HID + h * DH + c * 8);
    }
    load_kv(0);
    CP_COMMIT();

    float s[8][4];
    float o[16][4];
    #pragma unroll
    for (int j = 0; j < 16; ++j)
        #pragma unroll
        for (int c = 0; c < 4; ++c) o[j][c] = 0.f;
    float m0 = -1e30f, m1 = -1e30f, l0 = 0.f, l1 = 0.f;

    const int r0g = q0 + w * 16 + (lane >> 2);
    const int r1g = r0g + 8;
    const int c0l = (lane & 3) * 2;

    for (int t = 0; t < T; ++t) {
        const int k0 = t * 64;
        const int st = t & 1;
        const bool active = (q0 + w * 16 + 15) >= k0;

        CP_WAIT(0);
        __syncthreads();
        if (t + 1 < T) {
            load_kv(t + 1);
            CP_COMMIT();
        }

        if (active) {
            const uint32_t pK = base + SM_ST + st * STG_B;
            const uint32_t pV = pK + 17408;
            const int* mk_s = (const int*)(sm + SM_MK + st * 256);

            #pragma unroll
            for (int j = 0; j < 8; ++j)
                #pragma unroll
                for (int c = 0; c < 4; ++c) s[j][c] = 0.f;

            #pragma unroll
            for (int kc = 0; kc < 8; ++kc) {
                const uint32_t offa =
                    ((w * 16 + (lane & 15)) * QSTR + kc * 16 + ((lane >> 4) << 3)) * 2;
                uint32_t aq[4];
                ldsm_x4(aq, base + SM_Q + offa);
                #pragma unroll
                for (int g = 0; g < 4; ++g) {
                    const uint32_t offb =
                        ((g * 16 + (lane & 7) + ((lane >> 4) << 3)) * QSTR +
                         kc * 16 + (((lane >> 3) & 1) << 3)) * 2;
                    uint32_t bh[4];
                    ldsm_x4(bh, pK + offb);
                    mma_f16(s[2*g],   aq, &bh[0]);
                    mma_f16(s[2*g+1], aq, &bh[2]);
                }
            }

            float mx0 = -1e30f, mx1 = -1e30f;
            #pragma unroll
            for (int j = 0; j < 8; ++j) {
                const int cg = k0 + j * 8 + c0l;
                const int mk0 = mk_s[j * 8 + c0l];
                const int mk1 = mk_s[j * 8 + c0l + 1];
                s[j][0] = (cg     <= r0g && mk0) ? s[j][0] : -1e30f;
                s[j][1] = (cg + 1 <= r0g && mk1) ? s[j][1] : -1e30f;
                s[j][2] = (cg     <= r1g && mk0) ? s[j][2] : -1e30f;
                s[j][3] = (cg + 1 <= r1g && mk1) ? s[j][3] : -1e30f;
                mx0 = fmaxf(mx0, fmaxf(s[j][0], s[j][1]));
                mx1 = fmaxf(mx1, fmaxf(s[j][2], s[j][3]));
            }
            mx0 = fmaxf(mx0, __shfl_xor_sync(0xffffffff, mx0, 1));
            mx0 = fmaxf(mx0, __shfl_xor_sync(0xffffffff, mx0, 2));
            mx1 = fmaxf(mx1, __shfl_xor_sync(0xffffffff, mx1, 1));
            mx1 = fmaxf(mx1, __shfl_xor_sync(0xffffffff, mx1, 2));
            const float mn0 = fmaxf(m0, mx0), mn1 = fmaxf(m1, mx1);
            const float f0 = ex2(m0 - mn0), f1 = ex2(m1 - mn1);
            m0 = mn0; m1 = mn1;
            float sum0 = 0.f, sum1 = 0.f;
            #pragma unroll
            for (int j = 0; j < 8; ++j) {
                s[j][0] = ex2(s[j][0] - mn0);
                s[j][1] = ex2(s[j][1] - mn0);
                s[j][2] = ex2(s[j][2] - mn1);
                s[j][3] = ex2(s[j][3] - mn1);
                sum0 += s[j][0] + s[j][1];
                sum1 += s[j][2] + s[j][3];
            }
            sum0 += __shfl_xor_sync(0xffffffff, sum0, 1);
            sum0 += __shfl_xor_sync(0xffffffff, sum0, 2);
            sum1 += __shfl_xor_sync(0xffffffff, sum1, 1);
            sum1 += __shfl_xor_sync(0xffffffff, sum1, 2);
            l0 = l0 * f0 + sum0;
            l1 = l1 * f1 + sum1;
            #pragma unroll
            for (int j = 0; j < 16; ++j) {
                o[j][0] *= f0; o[j][1] *= f0;
                o[j][2] *= f1; o[j][3] *= f1;
            }

            #pragma unroll
            for (int kc = 0; kc < 4; ++kc) {
                uint32_t ap[4];
                ap[0] = packh2(s[2*kc][0],   s[2*kc][1]);
                ap[1] = packh2(s[2*kc][2],   s[2*kc][3]);
                ap[2] = packh2(s[2*kc+1][0], s[2*kc+1][1]);
                ap[3] = packh2(s[2*kc+1][2], s[2*kc+1][3]);
                #pragma unroll
                for (int g = 0; g < 8; ++g) {
                    const uint32_t offb =
                        ((g * 16 + (lane & 7) + ((lane >> 4) << 3)) * VSTR +
                         kc * 16 + (((lane >> 3) & 1) << 3)) * 2;
                    uint32_t bh[4];
                    ldsm_x4(bh, pV + offb);
                    mma_f16(o[2*g],   ap, &bh[0]);
                    mma_f16(o[2*g+1], ap, &bh[2]);
                }
            }
        }
    }

    const float inv0 = 1.f / l0, inv1 = 1.f / l1;
    const size_t base0 = (size_t)(b * SEQ + r0g) * HID + h * DH;
    const size_t base1 = (size_t)(b * SEQ + r1g) * HID + h * DH;
    #pragma unroll
    for (int j = 0; j < 16; ++j) {
        const int col = j * 8 + c0l;
        *(uint32_t*)&OH[base0 + col] = packh2(o[j][0] * inv0, o[j][1] * inv0);
        *(uint32_t*)&OH[base1 + col] = packh2(o[j][2] * inv1, o[j][3] * inv1);
    }
}

// ---------------------------------------------------------------------------
// Launch
// ---------------------------------------------------------------------------
extern "C" void kernel_launch(void* const* d_in, const int* in_sizes, int n_in,
                              void* d_out, int out_size)
{
    const float* x    = (const float*)d_in[0];
    const int*   mask = (const int*)  d_in[1];
    const float* Wq   = (const float*)d_in[2];
    const float* bq   = (const float*)d_in[3];
    const float* Wk   = (const float*)d_in[4];
    const float* bk   = (const float*)d_in[5];
    const float* Wv   = (const float*)d_in[6];
    const float* bv   = (const float*)d_in[7];
    const float* Wo   = (const float*)d_in[8];
    const float* bo   = (const float*)d_in[9];
    float* out = (float*)d_out;

    void *pxh, *pqs, *pkh, *pvth, *pah, *pwh, *pwoh;
    cudaGetSymbolAddress(&pxh, g_xh);
    cudaGetSymbolAddress(&pqs, g_qs);
    cudaGetSymbolAddress(&pkh, g_kh);
    cudaGetSymbolAddress(&pvth, g_vth);
    cudaGetSymbolAddress(&pah, g_ah);
    cudaGetSymbolAddress(&pwh, g_wh);
    cudaGetSymbolAddress(&pwoh, g_woh);

    // --- single merged converter ---
    conv_kernel<<<WCONV_BLOCKS + XCONV_BLOCKS, 256>>>(
        x, Wq, Wk, Wv, Wo,
        (__half*)pxh, (__half*)pwh, (__half*)pwoh);

    // --- fused QKV projection (128 thr, 64x64 warp tiles) ---
    cudaFuncSetAttribute(gemm_qkv, cudaFuncAttributeMaxDynamicSharedMemorySize,
                         GEMM_SMEM);
    cudaFuncSetAttribute(gemm_o, cudaFuncAttributeMaxDynamicSharedMemorySize,
                         GEMM_SMEM);
    gemm_qkv<<<dim3(NQKV / 128, MTOT / 128), 128, GEMM_SMEM>>>(
        (const __half*)pxh, (const __half*)pwh, bq, bk, bv,
        (__half*)pqs, (__half*)pkh, (__half*)pvth);

    // --- fp16 flash attention (2 CTAs/SM, LPT) ---
    cudaFuncSetAttribute(attn_hmma, cudaFuncAttributeMaxDynamicSharedMemorySize,
                         ATTN_SMEM);
    attn_hmma<<<dim3(NH, SEQ / 128, BATCH), 256, ATTN_SMEM>>>(
        (const __half*)pqs, (const __half*)pkh, (const __half*)pvth,
        mask, (__half*)pah);

    // --- output projection (128 thr, 64x64 warp tiles) ---
    gemm_o<<<dim3(HID / 128, MTOT / 128), 128, GEMM_SMEM>>>(
        (const __half*)pah, (const __half*)pwoh, bo, out);
}

// round 16
// speedup vs baseline: 1.0291x; 1.0291x over previous
#include <cuda_runtime.h>
#include <cuda_bf16.h>
#include <cuda_fp16.h>
#include <cstdint>
#include <math.h>

// ---------------------------------------------------------------------------
// Problem constants
// ---------------------------------------------------------------------------
#define BATCH   2
#define SEQ     2048
#define HID     2048
#define NH      16
#define NKV     4
#define DH      128
#define KVW     (NKV * DH)          // 512
#define MTOT    (BATCH * SEQ)       // 4096
#define GROUPS  (NH / NKV)          // 4
#define GEMM_K  2048
#define NQKV    (HID + 2 * KVW)     // 3072

// ---------------------------------------------------------------------------
// PTX helpers — ONLY non-'a' features (mma.sync / ldmatrix / cp.async).
// ---------------------------------------------------------------------------
__device__ __forceinline__ uint32_t smem_to_u32(const void* p) {
    uint32_t a;
    asm("{ .reg .u64 t; cvta.to.shared.u64 t, %1; cvt.u32.u64 %0, t; }"
        : "=r"(a) : "l"(p));
    return a;
}
#define CP_ASYNC16(dst, src) \
    asm volatile("cp.async.cg.shared.global [%0], [%1], 16;" \
                 :: "r"(dst), "l"(src))
#define CP_ASYNC4(dst, src) \
    asm volatile("cp.async.ca.shared.global [%0], [%1], 4;" \
                 :: "r"(dst), "l"(src))
#define CP_COMMIT() asm volatile("cp.async.commit_group;")
#define CP_WAIT(n)  asm volatile("cp.async.wait_group %0;" :: "n"(n))

__device__ __forceinline__ void ldsm_x4(uint32_t* r, uint32_t addr) {
    asm volatile("ldmatrix.sync.aligned.m8n8.x4.shared.b16 {%0,%1,%2,%3}, [%4];"
                 : "=r"(r[0]), "=r"(r[1]), "=r"(r[2]), "=r"(r[3]) : "r"(addr));
}
__device__ __forceinline__ void mma_f16(float* d, const uint32_t* a,
                                        const uint32_t* b) {
    asm volatile(
        "mma.sync.aligned.m16n8k16.row.col.f32.f16.f16.f32 "
        "{%0,%1,%2,%3}, {%4,%5,%6,%7}, {%8,%9}, {%0,%1,%2,%3};"
        : "+f"(d[0]), "+f"(d[1]), "+f"(d[2]), "+f"(d[3])
        : "r"(a[0]), "r"(a[1]), "r"(a[2]), "r"(a[3]), "r"(b[0]), "r"(b[1]));
}
__device__ __forceinline__ uint32_t packh2(float x, float y) {
    __half2 h(__float2half(x), __float2half(y));
    return *reinterpret_cast<uint32_t*>(&h);
}
__device__ __forceinline__ float ex2(float x) {
    float r;
    asm("ex2.approx.f32 %0, %1;" : "=f"(r) : "f"(x));
    return r;
}

// ---------------------------------------------------------------------------
// Scratch buffers
// ---------------------------------------------------------------------------
__device__ __half g_xh[(size_t)MTOT * HID];           // x single fp16
__device__ __half g_qs[(size_t)MTOT * HID];           // q single fp16 (pre-scaled)
__device__ __half g_kh[(size_t)MTOT * KVW];           // k single fp16
__device__ __half g_vth[(size_t)MTOT * KVW];          // VT single fp16 [B*KVW, SEQ]
__device__ __half g_ah[(size_t)MTOT * HID];           // attn out fp16
__device__ __half g_wh[(size_t)NQKV * HID];           // [Wq;Wk;Wv] T, single fp16
__device__ __half g_woh[(size_t)HID * HID];           // Wo T, single fp16

// ---------------------------------------------------------------------------
// Single merged converter: x -> fp16 AND all 4 weights transposed -> fp16.
// ---------------------------------------------------------------------------
#define WCONV_BLOCKS (160 * 64)
#define XCONV_BLOCKS (MTOT * HID / 4 / 256)   // 8192

__global__ void conv_kernel(const float* __restrict__ x,
                            const float* __restrict__ Wq,
                            const float* __restrict__ Wk,
                            const float* __restrict__ Wv,
                            const float* __restrict__ Wo,
                            __half* __restrict__ xh,
                            __half* __restrict__ wh,
                            __half* __restrict__ woh)
{
    const int bx  = blockIdx.x;
    const int tid = threadIdx.x;

    if (bx >= WCONV_BLOCKS) {
        const int i = (bx - WCONV_BLOCKS) * 256 + tid;
        float4 v = ((const float4*)x)[i];
        ((uint32_t*)xh)[2*i]   = packh2(v.x, v.y);
        ((uint32_t*)xh)[2*i+1] = packh2(v.z, v.w);
        return;
    }

    const int wmat = bx >> 6;
    const int by   = bx & 63;
    const float* W;
    __half* Th;
    int N, nblk;
    if (wmat < 64)      { W = Wq; Th = wh;  N = HID; nblk = wmat; }
    else if (wmat < 80) { W = Wk; Th = wh + (size_t)HID * GEMM_K;  N = KVW; nblk = wmat - 64; }
    else if (wmat < 96) { W = Wv; Th = wh + (size_t)(HID + KVW) * GEMM_K; N = KVW; nblk = wmat - 80; }
    else                { W = Wo; Th = woh; N = HID; nblk = wmat - 96; }

    __shared__ float t[32][33];
    const int tx = tid & 31, ty = tid >> 5;
    const int n  = nblk * 32 + tx;
    const int kb = by * 32;
    #pragma unroll
    for (int j = 0; j < 32; j += 8)
        t[ty + j][tx] = W[(size_t)(kb + ty + j) * N + n];
    __syncthreads();
    const int k  = kb + tx;
    const int nb = nblk * 32;
    #pragma unroll
    for (int j = 0; j < 32; j += 8) {
        float v = t[tx][ty + j];
        Th[(size_t)(nb + ty + j) * GEMM_K + k] = __float2half(v);
    }
}

// ---------------------------------------------------------------------------
// fp16 HMMA GEMM mainloop (R14 config: 256 thr, 8 warps, 64x32 warp tiles).
// KC=64 chunks, 3-stage pipeline, ONE sync per chunk, bias in smem.
// ---------------------------------------------------------------------------
#define KC        64
#define AS_STRIDE 72
#define MAT_B     (128 * AS_STRIDE * 2)   // 18432 bytes
#define STAGE_B   (2 * MAT_B)             // 36864 bytes
#define NCHUNK    (GEMM_K / KC)           // 32
#define SM_BIAS   (3 * STAGE_B)           // 110592
#define GEMM_SMEM (SM_BIAS + 512)         // 111104

#define GEMM_MAINLOOP_F16(AhP, BhP, BIAS_SRC)                                   \
    float acc[4][4][4];                                                         \
    _Pragma("unroll")                                                           \
    for (int a = 0; a < 4; ++a)                                                 \
        _Pragma("unroll")                                                       \
        for (int b2 = 0; b2 < 4; ++b2)                                          \
            _Pragma("unroll")                                                   \
            for (int c = 0; c < 4; ++c) acc[a][b2][c] = 0.f;                    \
    const __half* mats[2] = {AhP, BhP};                                         \
    auto load_stage = [&](int s, int k0) {                                      \
        const uint32_t st = smem_base + s * STAGE_B;                            \
        _Pragma("unroll")                                                       \
        for (int mat = 0; mat < 2; ++mat) {                                     \
            const __half* src = mats[mat];                                      \
            const int r0 = (mat < 1) ? m0 : n0;                                 \
            const uint32_t dstb = st + mat * MAT_B;                             \
            _Pragma("unroll")                                                   \
            for (int it = 0; it < 4; ++it) {                                    \
                const int idx = it * 256 + tid;                                 \
                const int row = idx >> 3;                                       \
                const int k8  = idx & 7;                                        \
                const void* sp = src + (size_t)(r0 + row) * GEMM_K + k0 + k8*8; \
                const uint32_t dp = dstb + row * (AS_STRIDE * 2) + k8 * 16;     \
                CP_ASYNC16(dp, sp);                                             \
            }                                                                   \
        }                                                                       \
    };                                                                          \
    if (tid < 32) CP_ASYNC16(smem_base + SM_BIAS + tid * 16, (BIAS_SRC) + tid * 4); \
    load_stage(0, 0);                                                           \
    CP_COMMIT();                                                                \
    load_stage(1, KC);                                                          \
    CP_COMMIT();                                                                \
    for (int c = 0; c < NCHUNK; ++c) {                                          \
        if (c + 1 < NCHUNK) { CP_WAIT(1); } else { CP_WAIT(0); }                \
        __syncthreads();                                                        \
        if (c + 2 < NCHUNK) {                                                   \
            load_stage((c + 2) % 3, (c + 2) * KC);                              \
            CP_COMMIT();                                                        \
        }                                                                       \
        const uint32_t stg = smem_base + (c % 3) * STAGE_B;                     \
        const uint32_t pA  = stg;                                               \
        const uint32_t pB  = stg + MAT_B;                                       \
        _Pragma("unroll")                                                       \
        for (int ks = 0; ks < 4; ++ks) {                                        \
            const int kcol = ks * 16;                                           \
            uint32_t bh[8];                                                     \
            _Pragma("unroll")                                                   \
            for (int p = 0; p < 2; ++p) {                                       \
                const int nrow = wn * 32 + p * 16 + (lane & 7) + ((lane>>4)<<3);\
                const int kk   = kcol + (((lane >> 3) & 1) << 3);               \
                const uint32_t off = (nrow * AS_STRIDE + kk) * 2;               \
                ldsm_x4(&bh[p * 4], pB + off);                                  \
            }                                                                   \
            _Pragma("unroll")                                                   \
            for (int mt = 0; mt < 4; ++mt) {                                    \
                const int mrow = wm * 64 + mt * 16 + (lane & 15);               \
                const int kk2  = kcol + ((lane >> 4) << 3);                     \
                const uint32_t offa = (mrow * AS_STRIDE + kk2) * 2;             \
                uint32_t afr[4];                                                \
                ldsm_x4(afr, pA + offa);                                        \
                _Pragma("unroll")                                               \
                for (int nt = 0; nt < 4; ++nt) mma_f16(acc[mt][nt], afr, &bh[nt*2]); \
            }                                                                   \
        }                                                                       \
    }

// ---------------------------------------------------------------------------
// Fused QKV projection (R14 config restored)
// ---------------------------------------------------------------------------
#define ATT_SCL (0.08838834764831845f * 1.4426950408889634f)

__global__ void __launch_bounds__(256, 2)
gemm_qkv(const __half* __restrict__ Ah, const __half* __restrict__ Bh,
         const float* __restrict__ bq, const float* __restrict__ bk,
         const float* __restrict__ bv,
         __half* __restrict__ Qs, __half* __restrict__ Kh,
         __half* __restrict__ VT)
{
    extern __shared__ __align__(128) char smem[];
    const uint32_t smem_base = smem_to_u32(smem);
    const int tid  = threadIdx.x;
    const int warp = tid >> 5;
    const int lane = tid & 31;
    const int wm   = warp >> 2;
    const int wn   = warp & 3;
    const int m0   = blockIdx.y * 128;
    const int n0   = blockIdx.x * 128;

    const float* bsrc = (n0 < HID) ? (bq + n0)
                       : (n0 < HID + KVW) ? (bk + n0 - HID)
                       : (bv + n0 - HID - KVW);

    GEMM_MAINLOOP_F16(Ah, Bh, bsrc)

    const float* bias_s = (const float*)(smem + SM_BIAS);

    #pragma unroll
    for (int mt = 0; mt < 4; ++mt)
        #pragma unroll
        for (int rh = 0; rh < 2; ++rh) {
            const int row = m0 + wm * 64 + mt * 16 + (lane >> 2) + rh * 8;
            #pragma unroll
            for (int nt = 0; nt < 4; ++nt) {
                const int cl  = wn * 32 + nt * 8 + (lane & 3) * 2;
                const int col = n0 + cl;
                const float b0 = bias_s[cl], b1 = bias_s[cl + 1];
                if (n0 < HID) {
                    const float v0 = (acc[mt][nt][rh*2+0] + b0) * ATT_SCL;
                    const float v1 = (acc[mt][nt][rh*2+1] + b1) * ATT_SCL;
                    *(uint32_t*)&Qs[(size_t)row * HID + col] = packh2(v0, v1);
                } else if (n0 < HID + KVW) {
                    const int c2 = col - HID;
                    const float v0 = acc[mt][nt][rh*2+0] + b0;
                    const float v1 = acc[mt][nt][rh*2+1] + b1;
                    *(uint32_t*)&Kh[(size_t)row * KVW + c2] = packh2(v0, v1);
                } else {
                    const int c2 = col - HID - KVW;
                    const int bb = row >> 11;
                    const int ss = row & (SEQ - 1);
                    const float v0 = acc[mt][nt][rh*2+0] + b0;
                    const float v1 = acc[mt][nt][rh*2+1] + b1;
                    VT[((size_t)bb * KVW + c2)     * SEQ + ss] = __float2half(v0);
                    VT[((size_t)bb * KVW + c2 + 1) * SEQ + ss] = __float2half(v1);
                }
            }
        }
}

// ---------------------------------------------------------------------------
// O-projection GEMM (R14 config restored)
// ---------------------------------------------------------------------------
__global__ void __launch_bounds__(256, 2)
gemm_o(const __half* __restrict__ Ah, const __half* __restrict__ Bh,
       const float* __restrict__ bias, float* __restrict__ C)
{
    extern __shared__ __align__(128) char smem[];
    const uint32_t smem_base = smem_to_u32(smem);
    const int tid  = threadIdx.x;
    const int warp = tid >> 5;
    const int lane = tid & 31;
    const int wm   = warp >> 2;
    const int wn   = warp & 3;
    const int m0   = blockIdx.y * 128;
    const int n0   = blockIdx.x * 128;

    GEMM_MAINLOOP_F16(Ah, Bh, bias + n0)

    const float* bias_s = (const float*)(smem + SM_BIAS);

    #pragma unroll
    for (int mt = 0; mt < 4; ++mt)
        #pragma unroll
        for (int rh = 0; rh < 2; ++rh) {
            const int row = m0 + wm * 64 + mt * 16 + (lane >> 2) + rh * 8;
            #pragma unroll
            for (int nt = 0; nt < 4; ++nt) {
                const int cl  = wn * 32 + nt * 8 + (lane & 3) * 2;
                const int col = n0 + cl;
                float2 v;
                v.x = acc[mt][nt][rh*2+0] + bias_s[cl];
                v.y = acc[mt][nt][rh*2+1] + bias_s[cl + 1];
                *(float2*)&C[(size_t)row * HID + col] = v;
            }
        }
}

// ---------------------------------------------------------------------------
// fp16 FlashAttention: 64 q-rows x 64 kv tiles, 4 warps (16 q-rows each).
// Finer q-granularity: heaviest CTA = 16 full-equiv units << 28.5 avg -> LPT
// balances makespan to ~average. All tiles active (diagonal via causal mask).
// Grid (NH, SEQ/64, BATCH), qb reversed on slow axis.
// ---------------------------------------------------------------------------
#define QSTR 136
#define VSTR 72
#define SM_Q   0
#define SM_ST  17408                 // Q is 64 rows * 272B
#define STG_B  35840                 // 17408 (K) + 18432 (V)
#define SM_MK  (SM_ST + 2 * STG_B)   // 89088
#define ATTN_SMEM (SM_MK + 512)      // 89600

__global__ void __launch_bounds__(128, 2)
attn_hmma(const __half* __restrict__ Qs, const __half* __restrict__ Kh,
          const __half* __restrict__ VTh, const int* __restrict__ mask,
          __half* __restrict__ OH)
{
    extern __shared__ __align__(128) char sm[];
    const uint32_t base = smem_to_u32(sm);
    const int tid = threadIdx.x;
    const int w    = tid >> 5;        // 0..3
    const int lane = tid & 31;
    const int h  = blockIdx.x;
    const int qb = (int)gridDim.y - 1 - (int)blockIdx.y;   // heavy-first (LPT)
    const int b  = blockIdx.z;
    const int q0 = qb * 64;
    const int kvh = h >> 2;
    const int T = qb + 1;

    auto load_kv = [&](int t) {
        const int k0 = t * 64;
        const int s  = t & 1;
        const uint32_t kdst = base + SM_ST + s * STG_B;
        #pragma unroll
        for (int i = 0; i < 8; ++i) {
            const int idx = i * 128 + tid;
            const int row = idx >> 4, c = idx & 15;
            CP_ASYNC16(kdst + row * 272 + c * 16,
                       Kh + (size_t)(b * SEQ + k0 + row) * KVW + kvh * DH + c * 8);
        }
        const uint32_t vdst = kdst + 17408;
        #pragma unroll
        for (int i = 0; i < 8; ++i) {
            const int idx = i * 128 + tid;
            const int row = idx >> 3, c = idx & 7;
            CP_ASYNC16(vdst + row * 144 + c * 16,
                       VTh + (size_t)(b * KVW + kvh * DH + row) * SEQ + k0 + c * 8);
        }
        if (tid < 64)
            CP_ASYNC4(base + SM_MK + s * 256 + tid * 4, mask + b * SEQ + k0 + tid);
    };

    // prologue: Q (64 rows) + KV(0)
    #pragma unroll
    for (int i = 0; i < 8; ++i) {
        const int idx = i * 128 + tid;
        const int row = idx >> 4, c = idx & 15;
        CP_ASYNC16(base + SM_Q + row * 272 + c * 16,
                   Qs + (size_t)(b * SEQ + q0 + row) * HID + h * DH + c * 8);
    }
    load_kv(0);
    CP_COMMIT();

    float s[8][4];
    float o[16][4];
    #pragma unroll
    for (int j = 0; j < 16; ++j)
        #pragma unroll
        for (int c = 0; c < 4; ++c) o[j][c] = 0.f;
    float m0 = -1e30f, m1 = -1e30f, l0 = 0.f, l1 = 0.f;

    const int r0g = q0 + w * 16 + (lane >> 2);
    const int r1g = r0g + 8;
    const int c0l = (lane & 3) * 2;

    for (int t = 0; t < T; ++t) {
        const int k0 = t * 64;
        const int st = t & 1;

        CP_WAIT(0);
        __syncthreads();
        if (t + 1 < T) {
            load_kv(t + 1);
            CP_COMMIT();
        }

        const uint32_t pK = base + SM_ST + st * STG_B;
        const uint32_t pV = pK + 17408;
        const int* mk_s = (const int*)(sm + SM_MK + st * 256);

        #pragma unroll
        for (int j = 0; j < 8; ++j)
            #pragma unroll
            for (int c = 0; c < 4; ++c) s[j][c] = 0.f;

        // S = Q*K
        #pragma unroll
        for (int kc = 0; kc < 8; ++kc) {
            const uint32_t offa =
                ((w * 16 + (lane & 15)) * QSTR + kc * 16 + ((lane >> 4) << 3)) * 2;
            uint32_t aq[4];
            ldsm_x4(aq, base + SM_Q + offa);
            #pragma unroll
            for (int g = 0; g < 4; ++g) {
                const uint32_t offb =
                    ((g * 16 + (lane & 7) + ((lane >> 4) << 3)) * QSTR +
                     kc * 16 + (((lane >> 3) & 1) << 3)) * 2;
                uint32_t bh[4];
                ldsm_x4(bh, pK + offb);
                mma_f16(s[2*g],   aq, &bh[0]);
                mma_f16(s[2*g+1], aq, &bh[2]);
            }
        }

        // mask + online softmax (base-2 domain)
        float mx0 = -1e30f, mx1 = -1e30f;
        #pragma unroll
        for (int j = 0; j < 8; ++j) {
            const int cg = k0 + j * 8 + c0l;
            const int mk0 = mk_s[j * 8 + c0l];
            const int mk1 = mk_s[j * 8 + c0l + 1];
            s[j][0] = (cg     <= r0g && mk0) ? s[j][0] : -1e30f;
            s[j][1] = (cg + 1 <= r0g && mk1) ? s[j][1] : -1e30f;
            s[j][2] = (cg     <= r1g && mk0) ? s[j][2] : -1e30f;
            s[j][3] = (cg + 1 <= r1g && mk1) ? s[j][3] : -1e30f;
            mx0 = fmaxf(mx0, fmaxf(s[j][0], s[j][1]));
            mx1 = fmaxf(mx1, fmaxf(s[j][2], s[j][3]));
        }
        mx0 = fmaxf(mx0, __shfl_xor_sync(0xffffffff, mx0, 1));
        mx0 = fmaxf(mx0, __shfl_xor_sync(0xffffffff, mx0, 2));
        mx1 = fmaxf(mx1, __shfl_xor_sync(0xffffffff, mx1, 1));
        mx1 = fmaxf(mx1, __shfl_xor_sync(0xffffffff, mx1, 2));
        const float mn0 = fmaxf(m0, mx0), mn1 = fmaxf(m1, mx1);
        const float f0 = ex2(m0 - mn0), f1 = ex2(m1 - mn1);
        m0 = mn0; m1 = mn1;
        float sum0 = 0.f, sum1 = 0.f;
        #pragma unroll
        for (int j = 0; j < 8; ++j) {
            s[j][0] = ex2(s[j][0] - mn0);
            s[j][1] = ex2(s[j][1] - mn0);
            s[j][2] = ex2(s[j][2] - mn1);
            s[j][3] = ex2(s[j][3] - mn1);
            sum0 += s[j][0] + s[j][1];
            sum1 += s[j][2] + s[j][3];
        }
        sum0 += __shfl_xor_sync(0xffffffff, sum0, 1);
        sum0 += __shfl_xor_sync(0xffffffff, sum0, 2);
        sum1 += __shfl_xor_sync(0xffffffff, sum1, 1);
        sum1 += __shfl_xor_sync(0xffffffff, sum1, 2);
        l0 = l0 * f0 + sum0;
        l1 = l1 * f1 + sum1;
        #pragma unroll
        for (int j = 0; j < 16; ++j) {
            o[j][0] *= f0; o[j][1] *= f0;
            o[j][2] *= f1; o[j][3] *= f1;
        }

        // O += P*V
        #pragma unroll
        for (int kc = 0; kc < 4; ++kc) {
            uint32_t ap[4];
            ap[0] = packh2(s[2*kc][0],   s[2*kc][1]);
            ap[1] = packh2(s[2*kc][2],   s[2*kc][3]);
            ap[2] = packh2(s[2*kc+1][0], s[2*kc+1][1]);
            ap[3] = packh2(s[2*kc+1][2], s[2*kc+1][3]);
            #pragma unroll
            for (int g = 0; g < 8; ++g) {
                const uint32_t offb =
                    ((g * 16 + (lane & 7) + ((lane >> 4) << 3)) * VSTR +
                     kc * 16 + (((lane >> 3) & 1) << 3)) * 2;
                uint32_t bh[4];
                ldsm_x4(bh, pV + offb);
                mma_f16(o[2*g],   ap, &bh[0]);
                mma_f16(o[2*g+1], ap, &bh[2]);
            }
        }
    }

    // epilogue: normalize, store single fp16
    const float inv0 = 1.f / l0, inv1 = 1.f / l1;
    const size_t base0 = (size_t)(b * SEQ + r0g) * HID + h * DH;
    const size_t base1 = (size_t)(b * SEQ + r1g) * HID + h * DH;
    #pragma unroll
    for (int j = 0; j < 16; ++j) {
        const int col = j * 8 + c0l;
        *(uint32_t*)&OH[base0 + col] = packh2(o[j][0] * inv0, o[j][1] * inv0);
        *(uint32_t*)&OH[base1 + col] = packh2(o[j][2] * inv1, o[j][3] * inv1);
    }
}

// ---------------------------------------------------------------------------
// Launch
// ---------------------------------------------------------------------------
extern "C" void kernel_launch(void* const* d_in, const int* in_sizes, int n_in,
                              void* d_out, int out_size)
{
    const float* x    = (const float*)d_in[0];
    const int*   mask = (const int*)  d_in[1];
    const float* Wq   = (const float*)d_in[2];
    const float* bq   = (const float*)d_in[3];
    const float* Wk   = (const float*)d_in[4];
    const float* bk   = (const float*)d_in[5];
    const float* Wv   = (const float*)d_in[6];
    const float* bv   = (const float*)d_in[7];
    const float* Wo   = (const float*)d_in[8];
    const float* bo   = (const float*)d_in[9];
    float* out = (float*)d_out;

    void *pxh, *pqs, *pkh, *pvth, *pah, *pwh, *pwoh;
    cudaGetSymbolAddress(&pxh, g_xh);
    cudaGetSymbolAddress(&pqs, g_qs);
    cudaGetSymbolAddress(&pkh, g_kh);
    cudaGetSymbolAddress(&pvth, g_vth);
    cudaGetSymbolAddress(&pah, g_ah);
    cudaGetSymbolAddress(&pwh, g_wh);
    cudaGetSymbolAddress(&pwoh, g_woh);

    // --- single merged converter ---
    conv_kernel<<<WCONV_BLOCKS + XCONV_BLOCKS, 256>>>(
        x, Wq, Wk, Wv, Wo,
        (__half*)pxh, (__half*)pwh, (__half*)pwoh);

    // --- fused QKV projection (R14 256-thr config) ---
    cudaFuncSetAttribute(gemm_qkv, cudaFuncAttributeMaxDynamicSharedMemorySize,
                         GEMM_SMEM);
    cudaFuncSetAttribute(gemm_o, cudaFuncAttributeMaxDynamicSharedMemorySize,
                         GEMM_SMEM);
    gemm_qkv<<<dim3(NQKV / 128, MTOT / 128), 256, GEMM_SMEM>>>(
        (const __half*)pxh, (const __half*)pwh, bq, bk, bv,
        (__half*)pqs, (__half*)pkh, (__half*)pvth);

    // --- fp16 flash attention (64-row q blocks, 4 warps, LPT) ---
    cudaFuncSetAttribute(attn_hmma, cudaFuncAttributeMaxDynamicSharedMemorySize,
                         ATTN_SMEM);
    attn_hmma<<<dim3(NH, SEQ / 64, BATCH), 128, ATTN_SMEM>>>(
        (const __half*)pqs, (const __half*)pkh, (const __half*)pvth,
        mask, (__half*)pah);

    // --- output projection (R14 256-thr config) ---
    gemm_o<<<dim3(HID / 128, MTOT / 128), 256, GEMM_SMEM>>>(
        (const __half*)pah, (const __half*)pwoh, bo, out);
}